// round 11
// baseline (speedup 1.0000x reference)
#include <cuda_runtime.h>
#include <cstdint>

// DatasetScoreMatchingLoss — bit-faithful replication of a sequential f32
// scatter-add segment_sum, parallelized by exponent-stage decomposition.
// R11: spin barriers reverted (R10 regression). Zeroing/atomic plumbing
// replaced by always-overwritten per-block partial arrays; planB/orchB
// derive their segment prefixes locally. 6 launches; pass2 in profile slot.

static constexpr int N_DATA  = 16777216;
static constexpr int CH      = 512;              // elements per chunk
static constexpr int NCHUNK  = N_DATA / CH;      // 32768
static constexpr int NB      = 32;               // 16 groups x 2 labels
static constexpr int NSEG    = 32;               // 1024 chunks per segment
static constexpr int BPS     = 128;              // pass-blocks per segment
static constexpr int NPART   = NSEG * BPS;       // 4096 partials per bucket
static constexpr int BCAP    = 512;              // boundary entries per bucket
static constexpr int RECW    = 76;               // hdr + <=72 j + incA + incB
static constexpr int JCAP    = RECW - 4;
static constexpr int SMAX    = 152;              // records per smem batch
static constexpr int LCAP    = 64;               // boundary chunks per orchB block
static constexpr unsigned M27 = (1u << 27) - 1u;
static constexpr unsigned long long M42 = (1ull << 42) - 1ull;
static constexpr unsigned long long C42 = 1ull << 42;

__device__ int                g_winner[N_DATA];      // zero-init; mark = i+1
__device__ unsigned           g_side[N_DATA];        // valid|bucket|j
__device__ unsigned long long g_p1[NB * NCHUNK];     // [b][chunk]: cnt<<42|sum_j
__device__ unsigned char      g_stage[NB * NCHUNK];  // stage | 0x80|ea | 0xFF
__device__ unsigned long long g_inc[NB * NCHUNK];    // [b][chunk]: rounded inc
__device__ unsigned long long g_segPart[NB * NPART]; // pass1 partials (cnt<<42|sum)
__device__ unsigned long long g_osegPart[NB * NPART];// pass2 partials (bd<<56|clean)
__device__ unsigned long long g_bndPre[NB * BCAP];
__device__ unsigned           g_bndJ[NB * BCAP * RECW];
__device__ unsigned long long g_cleanTot[NB];
__device__ int                g_nBnd[NB];
__device__ unsigned long long g_cntTot[NB];
__device__ float              g_S[NB];
__device__ unsigned           g_done;                // self-resetting counter

// encode one element -> side word (0 if invalid)
__device__ __forceinline__ unsigned enc(float s, int l, int g) {
    unsigned ul = (unsigned)l, ug = (unsigned)g;
    if ((ug < 16u) & (ul < 2u) & (s == s) & (s >= 0.0f) & (s < 1.0f)) {
        int j = (int)(s * 8388608.0f);          // exact: s multiple of 2^-23
        return 0x80000000u | ((ul + 2u * ug) << 23) | (unsigned)j;
    }
    return 0u;
}

// round_half_even(j / 2^e) for e>=1, j < 2^23
__device__ __forceinline__ unsigned rne_q(unsigned j, int e) {
    unsigned q = j >> e;
    unsigned r = j & ((1u << e) - 1u);
    unsigned half = 1u << (e - 1);
    q += (unsigned)((r > half) || (r == half && (q & 1u)));
    return q;
}

// ---------------------------------------------------------------- pass1
// Warp-per-chunk; also marks scatter winners; writes per-block partials
// (plain stores -> no zeroing, no atomics, graph-replay safe).
__global__ void __launch_bounds__(256)
pass1_kernel(const float4* __restrict__ s4, const int4* __restrict__ l4,
             const int4* __restrict__ g4, const int* __restrict__ indices,
             int B) {
    __shared__ unsigned acc[8][NB * 33];
    __shared__ unsigned long long tr[NB][8];
    int t = threadIdx.x, w = t >> 5, lane = t & 31;
    int chunk0 = blockIdx.x * 8, chunk = chunk0 + w;
    int seg = chunk0 >> 10, blkInSeg = blockIdx.x & (BPS - 1);

    int mi = blockIdx.x * 256 + t;              // fused mark (last-wins)
    if (mi < B) atomicMax(&g_winner[indices[mi]], mi + 1);

    unsigned* A = acc[w];
#pragma unroll
    for (int b = 0; b < NB; b++) A[b * 33 + lane] = 0u;

    int base4 = chunk * (CH / 4);
    float4 sv[4]; int4 lv[4]; int4 gv[4];
#pragma unroll
    for (int k = 0; k < 4; k++) {               // 12 LDG.128 in flight
        int i4 = base4 + k * 32 + lane;
        sv[k] = s4[i4]; lv[k] = l4[i4]; gv[k] = g4[i4];
    }
    __syncwarp();
    uint4* side4 = reinterpret_cast<uint4*>(g_side);
#pragma unroll
    for (int k = 0; k < 4; k++) {
        unsigned d0 = enc(sv[k].x, lv[k].x, gv[k].x);
        unsigned d1 = enc(sv[k].y, lv[k].y, gv[k].y);
        unsigned d2 = enc(sv[k].z, lv[k].z, gv[k].z);
        unsigned d3 = enc(sv[k].w, lv[k].w, gv[k].w);
        if (d0) A[((d0 >> 23) & 31u) * 33 + lane] += (1u << 27) + (d0 & 0x7FFFFFu);
        if (d1) A[((d1 >> 23) & 31u) * 33 + lane] += (1u << 27) + (d1 & 0x7FFFFFu);
        if (d2) A[((d2 >> 23) & 31u) * 33 + lane] += (1u << 27) + (d2 & 0x7FFFFFu);
        if (d3) A[((d3 >> 23) & 31u) * 33 + lane] += (1u << 27) + (d3 & 0x7FFFFFu);
        side4[base4 + k * 32 + lane] = make_uint4(d0, d1, d2, d3);
    }
    __syncwarp();
    unsigned long long tot = 0ull;
#pragma unroll
    for (int k = 0; k < 32; k++) {
        unsigned v = A[lane * 33 + k];
        tot += ((unsigned long long)(v >> 27) << 42) | (v & M27);
    }
    tr[lane][w] = tot;
    __syncthreads();
    int b = t >> 3, cw = t & 7;
    unsigned long long pv = tr[b][cw];
    g_p1[(size_t)b * NCHUNK + chunk0 + cw] = pv;
    unsigned long long sv2 = pv;                 // group-of-8 reduce
    sv2 += __shfl_down_sync(0xFFFFFFFFu, sv2, 4, 8);
    sv2 += __shfl_down_sync(0xFFFFFFFFu, sv2, 2, 8);
    sv2 += __shfl_down_sync(0xFFFFFFFFu, sv2, 1, 8);
    if (cw == 0)
        g_segPart[b * NPART + seg * BPS + blkInSeg] = sv2;   // plain store
}

// ---------------------------------------------------------------- patch
__global__ void patch_kernel(const float* __restrict__ probs,
                             const int* __restrict__ labels,
                             const int* __restrict__ groups,
                             const int* __restrict__ indices, int B) {
    int i = blockIdx.x * blockDim.x + threadIdx.x;
    if (i >= B) return;
    int idx = indices[i];
    if (g_winner[idx] != i + 1) return;
    unsigned oldside = g_side[idx];
    unsigned newside = enc(probs[i], labels[i], groups[i]);
    if (newside == oldside) return;
    int chunk = idx >> 9;
    int part = (chunk >> 3);                    // global pass-block id
    if (oldside & 0x80000000u) {
        unsigned b = (oldside >> 23) & 31u;
        unsigned long long d = C42 + (unsigned long long)(oldside & 0x7FFFFFu);
        atomicAdd(&g_p1[(size_t)b * NCHUNK + chunk], 0ull - d);
        atomicAdd(&g_segPart[b * NPART + part], 0ull - d);
    }
    if (newside & 0x80000000u) {
        unsigned b = (newside >> 23) & 31u;
        unsigned long long d = C42 + (unsigned long long)(newside & 0x7FFFFFu);
        atomicAdd(&g_p1[(size_t)b * NCHUNK + chunk], d);
        atomicAdd(&g_segPart[b * NPART + part], d);
    }
    g_side[idx] = newside;
}

// ---------------------------------------------------------------- planB
// grid (NSEG, NB). Each block derives all 32 segment totals of its bucket
// from the 4096 partials (no barrier, no atomics needed).
__global__ void __launch_bounds__(256)
planB_kernel() {
    int seg = blockIdx.x, b = blockIdx.y, t = threadIdx.x;
    __shared__ unsigned long long ss[NSEG];
    __shared__ unsigned long long sp[256];
    __shared__ unsigned long long sc[256];
    __shared__ unsigned long long segpre_sh;

    // derive segment totals: thread t sums 16 partials (within segment t/8)
    const unsigned long long* part = &g_segPart[b * NPART];
    unsigned long long ps = 0ull;
#pragma unroll
    for (int k = 0; k < 16; k++) ps += part[t * 16 + k];
    sp[t] = ps;
    __syncthreads();
    if (t < NSEG) {
        unsigned long long s = 0ull;
#pragma unroll
        for (int k = 0; k < 8; k++) s += sp[t * 8 + k];
        ss[t] = s;
    }
    __syncthreads();
    if (t == 0) {
        unsigned long long p = 0ull, tot = 0ull;
        for (int i = 0; i < NSEG; i++) { if (i < seg) p += ss[i]; tot += ss[i]; }
        segpre_sh = p;
        if (seg == 0) g_cntTot[b] = tot >> 42;
    }

    size_t base = (size_t)b * NCHUNK + seg * 1024 + t * 4;
    const ulonglong2* pp = reinterpret_cast<const ulonglong2*>(&g_p1[base]);
    ulonglong2 v01 = pp[0], v23 = pp[1];
    unsigned long long pv[4] = { v01.x, v01.y, v23.x, v23.y };
    sc[t] = pv[0] + pv[1] + pv[2] + pv[3];
    __syncthreads();
    for (int off = 1; off < 256; off <<= 1) {
        unsigned long long v = (t >= off) ? sc[t - off] : 0ull;
        __syncthreads();
        sc[t] += v;
        __syncthreads();
    }
    unsigned long long excl = (t > 0) ? sc[t - 1] : 0ull;
    unsigned long long P = (segpre_sh + excl) & M42;   // raw prefix (2^-23 units)

    unsigned char st4[4];
#pragma unroll
    for (int k = 0; k < 4; k++) {
        unsigned long long cs = pv[k] & M42;
        unsigned cnt = (unsigned)(pv[k] >> 42);
        unsigned char st;
        if (cnt == 0u) {
            st = 1;                               // empty chunk: clean, inc 0
        } else {
            unsigned long long hi = P + cs;
            int e2 = 63 - __clzll((long long)hi) - 23;
            if (e2 < 1) st = 0xFF;
            else {
                int sb = (3 * e2) / 2 + 2; if (sb > 40) sb = 40;
                unsigned long long sl = (1ull << sb) + (1ull << 22);
                if (P > sl) {
                    unsigned long long lo2 = P - sl, hi2 = hi + sl;
                    int ea = 63 - __clzll((long long)lo2) - 23;
                    int eb = 63 - __clzll((long long)hi2) - 23;
                    if (ea >= 1 && ea == eb)           st = (unsigned char)ea;
                    else if (ea >= 1 && eb == ea + 1)  st = (unsigned char)(0x80 | ea);
                    else                               st = 0xFF;
                } else st = 0xFF;
            }
        }
        st4[k] = st;
        P += cs;
    }
    *reinterpret_cast<uchar4*>(&g_stage[base]) =
        make_uchar4(st4[0], st4[1], st4[2], st4[3]);
}

// ---------------------------------------------------------------- pass2
// Warp-per-chunk; writes rounded incs + packed per-block partials.
__global__ void __launch_bounds__(256)
pass2_kernel() {
    __shared__ unsigned acc[8][NB * 33];
    __shared__ unsigned long long tr[NB][8];
    __shared__ unsigned char stg[8][NB];
    int t = threadIdx.x, w = t >> 5, lane = t & 31;
    int chunk0 = blockIdx.x * 8, chunk = chunk0 + w;
    int seg = chunk0 >> 10, blkInSeg = blockIdx.x & (BPS - 1);
    stg[w][lane] = g_stage[(size_t)lane * NCHUNK + chunk];
    unsigned* A = acc[w];
#pragma unroll
    for (int b = 0; b < NB; b++) A[b * 33 + lane] = 0u;
    __syncwarp();
    int base4 = chunk * (CH / 4);
    const uint4* side4 = reinterpret_cast<const uint4*>(g_side);
    uint4 sdv[4];
#pragma unroll
    for (int k = 0; k < 4; k++) sdv[k] = side4[base4 + k * 32 + lane];
#pragma unroll
    for (int k = 0; k < 4; k++) {
        unsigned ds[4] = { sdv[k].x, sdv[k].y, sdv[k].z, sdv[k].w };
#pragma unroll
        for (int c = 0; c < 4; c++) {
            unsigned side = ds[c];
            if (side & 0x80000000u) {
                unsigned b = (side >> 23) & 31u;
                int e = stg[w][b];
                if (e < 0x80) {
                    unsigned j = side & 0x7FFFFFu;
                    A[b * 33 + lane] += rne_q(j, e) << e;
                }
            }
        }
    }
    __syncwarp();
    unsigned long long tot = 0ull;
#pragma unroll
    for (int k = 0; k < 32; k++) tot += (unsigned long long)A[lane * 33 + k];
    tr[lane][w] = tot;
    __syncthreads();
    int b = t >> 3, cw = t & 7;
    unsigned long long pv = tr[b][cw];            // boundary chunks: pv==0
    g_inc[(size_t)b * NCHUNK + chunk0 + cw] = pv;
    unsigned long long bd = (stg[cw][b] & 0x80) ? 1ull : 0ull;
    unsigned long long svp = pv + (bd << 56);     // pack: bd<<56 | cleanSum
    svp += __shfl_down_sync(0xFFFFFFFFu, svp, 4, 8);
    svp += __shfl_down_sync(0xFFFFFFFFu, svp, 2, 8);
    svp += __shfl_down_sync(0xFFFFFFFFu, svp, 1, 8);
    if (cw == 0)
        g_osegPart[b * NPART + seg * BPS + blkInSeg] = svp;  // plain store
}

// ---------------------------------------------------------------- orchB
// grid (NSEG, NB). Derives segment clean/boundary prefixes from partials;
// gathers boundary records inline (no barrier).
__global__ void __launch_bounds__(256)
orchB_kernel() {
    int seg = blockIdx.x, b = blockIdx.y, t = threadIdx.x;
    __shared__ unsigned long long ssP[NSEG];
    __shared__ unsigned long long spP[256];
    __shared__ unsigned long long scC[256];
    __shared__ int scB[256];
    __shared__ unsigned long long segC_sh;
    __shared__ int segB_sh;
    __shared__ int locCh[LCAP];
    __shared__ int locKp[LCAP];
    __shared__ int locN;
    __shared__ unsigned jb[JCAP];
    __shared__ int wcnt[8];
    __shared__ int phN;
    int w = t >> 5, lane = t & 31;
    if (t == 0) locN = 0;

    // derive packed segment totals from pass2 partials
    const unsigned long long* part = &g_osegPart[b * NPART];
    unsigned long long ps = 0ull;
#pragma unroll
    for (int k = 0; k < 16; k++) ps += part[t * 16 + k];
    spP[t] = ps;
    __syncthreads();
    if (t < NSEG) {
        unsigned long long s = 0ull;
#pragma unroll
        for (int k = 0; k < 8; k++) s += spP[t * 8 + k];
        ssP[t] = s;
    }
    __syncthreads();
    if (t == 0) {
        unsigned long long pcs = 0ull, tC = 0ull; int pbs = 0, tB = 0;
        for (int i = 0; i < NSEG; i++) {
            unsigned long long cl = ssP[i] & ((1ull << 56) - 1ull);
            int bc = (int)(ssP[i] >> 56);
            if (i < seg) { pcs += cl; pbs += bc; }
            tC += cl; tB += bc;
        }
        segC_sh = pcs; segB_sh = pbs;
        if (seg == 0) { g_cleanTot[b] = tC; g_nBnd[b] = tB; }
    }
    __syncthreads();

    size_t base = (size_t)b * NCHUNK + seg * 1024 + t * 4;
    uchar4 st4 = *reinterpret_cast<const uchar4*>(&g_stage[base]);
    const ulonglong2* ip = reinterpret_cast<const ulonglong2*>(&g_inc[base]);
    ulonglong2 i01 = ip[0], i23 = ip[1];
    unsigned long long inc[4] = { i01.x, i01.y, i23.x, i23.y };
    unsigned char sts[4] = { st4.x, st4.y, st4.z, st4.w };

    unsigned long long pc = 0ull; int pb = 0;
#pragma unroll
    for (int k = 0; k < 4; k++) {
        if (sts[k] & 0x80) pb++;
        else pc += inc[k];
    }
    scC[t] = pc; scB[t] = pb;
    __syncthreads();
    for (int off = 1; off < 256; off <<= 1) {
        unsigned long long vC = (t >= off) ? scC[t - off] : 0ull;
        int vB = (t >= off) ? scB[t - off] : 0;
        __syncthreads();
        scC[t] += vC; scB[t] += vB;
        __syncthreads();
    }
    unsigned long long run = segC_sh + ((t > 0) ? scC[t - 1] : 0ull);
    int kpos = segB_sh + ((t > 0) ? scB[t - 1] : 0);
#pragma unroll
    for (int k = 0; k < 4; k++) {
        if (sts[k] & 0x80) {
            if (kpos < BCAP) {
                g_bndPre[b * BCAP + kpos] = run;
                int sl = atomicAdd(&locN, 1);
                if (sl < LCAP) {
                    locCh[sl] = seg * 1024 + t * 4 + k;
                    locKp[sl] = kpos;
                }
            }
            kpos++;
        } else run += inc[k];
    }
    __syncthreads();

    // inline gather per local boundary chunk (order-preserving compaction)
    int nloc = locN; if (nloc > LCAP) nloc = LCAP;
    for (int e = 0; e < nloc; e++) {
        int ch = locCh[e];
        unsigned* rec = &g_bndJ[(size_t)(b * BCAP + locKp[e]) * RECW];
        int cnt = 0;
        for (int ph = 0; ph < 2; ph++) {
            unsigned side = g_side[ch * CH + ph * 256 + t];
            bool valid = (side & 0x80000000u) &&
                         (((side >> 23) & 31u) == (unsigned)b);
            unsigned m = __ballot_sync(0xFFFFFFFFu, valid);
            if (lane == 0) wcnt[w] = __popc(m);
            __syncthreads();
            if (t == 0) {
                int s = 0;
                for (int q = 0; q < 8; q++) { int c = wcnt[q]; wcnt[q] = s; s += c; }
                phN = s;
            }
            __syncthreads();
            if (valid) {
                int pos = cnt + wcnt[w] + __popc(m & ((1u << lane) - 1u));
                if (pos < JCAP) jb[pos] = side & 0x7FFFFFu;
            }
            cnt += phN;
            __syncthreads();
        }
        if (t == 0) {
            if (cnt > JCAP) cnt = JCAP;
            unsigned st = g_stage[(size_t)b * NCHUNK + ch];
            rec[0] = (unsigned)cnt | (st << 16);
            for (int c = 0; c < cnt; c++) rec[1 + c] = jb[c];
            if ((st & 0x80) && st != 0xFFu) {
                int ea = (int)(st & 0x7Fu);
                unsigned iA = 0u, iB = 0u;
                for (int c = 0; c < cnt; c++) {
                    unsigned j = jb[c];
                    iA += rne_q(j, ea) << ea;
                    iB += rne_q(j, ea + 1) << (ea + 1);
                }
                rec[RECW - 2] = iA;
                rec[RECW - 1] = iB;
            }
        }
        __syncthreads();
    }
}

// Bit-exact IEEE f32 RNE add; v = accumulator*2^23 (<=24 sig bits), j<2^23.
__device__ __forceinline__ unsigned long long emul_add(unsigned long long v,
                                                       unsigned long long j) {
    unsigned long long tt = v + j;
    if (tt == 0ull) return 0ull;
    int nb = 64 - __clzll((long long)tt);
    if (nb <= 24) return tt;
    int sh = nb - 24;
    unsigned long long half = 1ull << (sh - 1);
    unsigned long long r = tt & ((1ull << sh) - 1ull);
    unsigned long long q = tt >> sh;
    q += (unsigned long long)((r > half) || (r == half && (q & 1ull)));
    return q << sh;
}

// ---------------------------------------------------------------- finalize
__device__ void finalize_body(float* out) {
    float var2[2], nn2[2];
    for (int lab = 0; lab < 2; lab++) {
        float avg[16], incl[16];
        for (int g = 0; g < 16; g++) {
            int b = lab + 2 * g;
            float sum = g_S[b];
            float cnt = (float)(long long)g_cntTot[b];
            avg[g]  = __fdiv_rn(sum, fmaxf(cnt, 1.0f));
            incl[g] = (cnt >= 10.0f) ? 1.0f : 0.0f;
        }
        float n = 0.0f, msum = 0.0f;
        for (int g = 0; g < 16; g++) {
            n    = __fadd_rn(n, incl[g]);
            msum = __fadd_rn(msum, __fmul_rn(avg[g], incl[g]));
        }
        float mean = __fdiv_rn(msum, fmaxf(n, 1.0f));
        float vsum = 0.0f;
        for (int g = 0; g < 16; g++) {
            float d  = __fadd_rn(avg[g], -mean);
            float d2 = __fmul_rn(d, d);
            vsum = __fadd_rn(vsum, __fmul_rn(incl[g], d2));
        }
        float var = __fdiv_rn(vsum, fmaxf(__fadd_rn(n, -1.0f), 1.0f));
        var2[lab] = var; nn2[lab] = n;
    }
    bool pos_ok = nn2[1] >= 2.0f, neg_ok = nn2[0] >= 2.0f;
    float loss;
    if (pos_ok && neg_ok) loss = __fmul_rn(0.5f, __fadd_rn(var2[1], var2[0]));
    else if (pos_ok)      loss = var2[1];
    else if (neg_ok)      loss = var2[0];
    else                  loss = 0.0f;
    out[0] = loss;
}

// ---------------------------------------------------------------- orchF
__global__ void __launch_bounds__(512)
orchF_kernel(float* __restrict__ out) {
    int b = blockIdx.x, t = threadIdx.x;
    __shared__ unsigned jrec[SMAX * RECW];
    __shared__ unsigned long long pre[SMAX];
    int nBnd = g_nBnd[b];
    if (nBnd > BCAP) nBnd = BCAP;

    unsigned long long v = 0ull, consumed = 0ull;
    for (int base = 0; base < nBnd; base += SMAX) {
        int nb2 = nBnd - base; if (nb2 > SMAX) nb2 = SMAX;
        const unsigned* src = &g_bndJ[(size_t)(b * BCAP + base) * RECW];
        for (int i = t; i < nb2 * RECW; i += 512) jrec[i] = src[i];
        for (int i = t; i < nb2; i += 512) pre[i] = g_bndPre[b * BCAP + base + i];
        __syncthreads();
        if (t == 0) {
            for (int kk = 0; kk < nb2; kk++) {
                v += pre[kk] - consumed;   // exact integer clean incs between
                consumed = pre[kk];
                const unsigned* r = &jrec[kk * RECW];
                unsigned hdr = r[0];
                int cnt = (int)(hdr & 0xFFFFu);
                unsigned st = hdr >> 16;
                bool done = false;
                if ((st & 0x80u) && st != 0xFFu && v >= (1ull << 23)) {
                    int ea = (int)(st & 0x7Fu);
                    int ev = 63 - __clzll((long long)v) - 23;
                    if (ev == ea) {
                        unsigned long long nv = v + (unsigned long long)r[RECW - 2];
                        if (63 - __clzll((long long)nv) - 23 == ea) { v = nv; done = true; }
                    } else if (ev == ea + 1) {
                        unsigned long long nv = v + (unsigned long long)r[RECW - 1];
                        if (63 - __clzll((long long)nv) - 23 == ea + 1) { v = nv; done = true; }
                    }
                }
                if (!done) {
                    for (int c = 1; c <= cnt; c++)
                        v = emul_add(v, (unsigned long long)r[c]);
                }
            }
        }
        __syncthreads();
    }
    if (t == 0) {
        v += g_cleanTot[b] - consumed;
        g_S[b] = (float)((double)v * (1.0 / 8388608.0));   // <=24 sig bits: exact
        __threadfence();
        unsigned prev = atomicAdd(&g_done, 1u);
        if (prev == NB - 1u) {
            g_done = 0u;               // self-reset for graph replay
            __threadfence();
            finalize_body(out);
        }
    }
}

// ---------------------------------------------------------------- launch
extern "C" void kernel_launch(void* const* d_in, const int* in_sizes, int n_in,
                              void* d_out, int out_size) {
    const float* probs   = (const float*)d_in[0];
    const int*   labels  = (const int*)d_in[1];
    const int*   groups  = (const int*)d_in[2];
    const int*   indices = (const int*)d_in[3];
    const float* sbuf    = (const float*)d_in[4];
    const int*   lbuf    = (const int*)d_in[5];
    const int*   gbuf    = (const int*)d_in[6];
    int B = in_sizes[0];

    pass1_kernel<<<NCHUNK / 8, 256>>>((const float4*)sbuf, (const int4*)lbuf,
                                      (const int4*)gbuf, indices, B);
    patch_kernel<<<(B + 127) / 128, 128>>>(probs, labels, groups, indices, B);
    planB_kernel<<<dim3(NSEG, NB), 256>>>();
    pass2_kernel<<<NCHUNK / 8, 256>>>();        // profile slot #4
    orchB_kernel<<<dim3(NSEG, NB), 256>>>();
    orchF_kernel<<<NB, 512>>>((float*)d_out);
}

// round 12
// speedup vs baseline: 1.1435x; 1.1435x over previous
#include <cuda_runtime.h>
#include <cstdint>

// DatasetScoreMatchingLoss — bit-faithful replication of a sequential f32
// scatter-add segment_sum, parallelized by exponent-stage decomposition.
// R12: R9 structure (best: 180.3us) + conflict-free smem accumulator layout
// (x32 stride, bank=lane in hot loop; diagonal conflict-free reduce).

static constexpr int N_DATA  = 16777216;
static constexpr int CH      = 512;              // elements per chunk
static constexpr int NCHUNK  = N_DATA / CH;      // 32768
static constexpr int NB      = 32;               // 16 groups x 2 labels
static constexpr int NSEG    = 32;               // 1024 chunks per segment
static constexpr int BCAP    = 512;              // boundary entries per bucket
static constexpr int RECW    = 76;               // hdr + <=72 j + incA + incB
static constexpr int JCAP    = RECW - 4;
static constexpr int SMAX    = 152;              // records per smem batch
static constexpr int LCAP    = 64;               // boundary chunks per orchB block
static constexpr unsigned M27 = (1u << 27) - 1u;
static constexpr unsigned long long M42 = (1ull << 42) - 1ull;
static constexpr unsigned long long C42 = 1ull << 42;

__device__ int                g_winner[N_DATA];      // zero-init; mark = i+1
__device__ unsigned           g_side[N_DATA];        // valid|bucket|j
__device__ unsigned long long g_p1[NB * NCHUNK];     // [b][chunk]: cnt<<42|sum_j
__device__ unsigned char      g_stage[NB * NCHUNK];  // stage | 0x80|ea | 0xFF
__device__ unsigned long long g_inc[NB * NCHUNK];    // [b][chunk]: rounded inc
__device__ unsigned long long g_segSum[NB * NSEG];
__device__ unsigned long long g_osegC[NB * NSEG];
__device__ int                g_osegB[NB * NSEG];
__device__ unsigned long long g_bndPre[NB * BCAP];
__device__ unsigned           g_bndJ[NB * BCAP * RECW];
__device__ unsigned long long g_cleanTot[NB];
__device__ int                g_nBnd[NB];
__device__ unsigned long long g_cntTot[NB];
__device__ float              g_S[NB];
__device__ unsigned           g_done;                // self-resetting counter

// ---------------------------------------------------------------- zero+mark
__global__ void zeromark_kernel(const int* __restrict__ indices, int B) {
    int i = blockIdx.x * blockDim.x + threadIdx.x;
    if (i < NB * NSEG) { g_segSum[i] = 0ull; g_osegC[i] = 0ull; g_osegB[i] = 0; }
    if (i < B) atomicMax(&g_winner[indices[i]], i + 1);   // last-wins
}

// encode one element -> side word (0 if invalid)
__device__ __forceinline__ unsigned enc(float s, int l, int g) {
    unsigned ul = (unsigned)l, ug = (unsigned)g;
    if ((ug < 16u) & (ul < 2u) & (s == s) & (s >= 0.0f) & (s < 1.0f)) {
        int j = (int)(s * 8388608.0f);          // exact: s multiple of 2^-23
        return 0x80000000u | ((ul + 2u * ug) << 23) | (unsigned)j;
    }
    return 0u;
}

// round_half_even(j / 2^e) for e>=1, j < 2^23
__device__ __forceinline__ unsigned rne_q(unsigned j, int e) {
    unsigned q = j >> e;
    unsigned r = j & ((1u << e) - 1u);
    unsigned half = 1u << (e - 1);
    q += (unsigned)((r > half) || (r == half && (q & 1u)));
    return q;
}

// ---------------------------------------------------------------- pass1
// Warp-per-chunk (512 elems, 16/lane), 8 chunks/block. Pre-scatter state.
// acc layout [b*32+lane]: hot-loop bank = lane (conflict-free for any b).
__global__ void __launch_bounds__(256)
pass1_kernel(const float4* __restrict__ s4, const int4* __restrict__ l4,
             const int4* __restrict__ g4) {
    __shared__ unsigned acc[8][NB * 32];
    __shared__ unsigned long long tr[NB][8];
    int t = threadIdx.x, w = t >> 5, lane = t & 31;
    int chunk0 = blockIdx.x * 8, chunk = chunk0 + w;
    int seg = chunk0 >> 10;
    unsigned* A = acc[w];
#pragma unroll
    for (int b = 0; b < NB; b++) A[b * 32 + lane] = 0u;

    int base4 = chunk * (CH / 4);
    float4 sv[4]; int4 lv[4]; int4 gv[4];
#pragma unroll
    for (int k = 0; k < 4; k++) {               // 12 LDG.128 in flight
        int i4 = base4 + k * 32 + lane;
        sv[k] = s4[i4]; lv[k] = l4[i4]; gv[k] = g4[i4];
    }
    __syncwarp();
    uint4* side4 = reinterpret_cast<uint4*>(g_side);
#pragma unroll
    for (int k = 0; k < 4; k++) {
        unsigned d0 = enc(sv[k].x, lv[k].x, gv[k].x);
        unsigned d1 = enc(sv[k].y, lv[k].y, gv[k].y);
        unsigned d2 = enc(sv[k].z, lv[k].z, gv[k].z);
        unsigned d3 = enc(sv[k].w, lv[k].w, gv[k].w);
        if (d0) A[((d0 >> 23) & 31u) * 32 + lane] += (1u << 27) + (d0 & 0x7FFFFFu);
        if (d1) A[((d1 >> 23) & 31u) * 32 + lane] += (1u << 27) + (d1 & 0x7FFFFFu);
        if (d2) A[((d2 >> 23) & 31u) * 32 + lane] += (1u << 27) + (d2 & 0x7FFFFFu);
        if (d3) A[((d3 >> 23) & 31u) * 32 + lane] += (1u << 27) + (d3 & 0x7FFFFFu);
        side4[base4 + k * 32 + lane] = make_uint4(d0, d1, d2, d3);
    }
    __syncwarp();
    // lane owns bucket=lane; diagonal read: bank (lane+k)&31, conflict-free
    unsigned long long tot = 0ull;
#pragma unroll
    for (int k = 0; k < 32; k++) {
        unsigned v = A[lane * 32 + ((lane + k) & 31)];
        tot += ((unsigned long long)(v >> 27) << 42) | (v & M27);
    }
    tr[lane][w] = tot;
    __syncthreads();
    int b = t >> 3, cw = t & 7;
    unsigned long long pv = tr[b][cw];
    g_p1[(size_t)b * NCHUNK + chunk0 + cw] = pv;
    unsigned long long sv2 = pv;                 // group-of-8 reduce
    sv2 += __shfl_down_sync(0xFFFFFFFFu, sv2, 4, 8);
    sv2 += __shfl_down_sync(0xFFFFFFFFu, sv2, 2, 8);
    sv2 += __shfl_down_sync(0xFFFFFFFFu, sv2, 1, 8);
    if (cw == 0) atomicAdd(&g_segSum[b * NSEG + seg], sv2);
}

// ---------------------------------------------------------------- patch
__global__ void patch_kernel(const float* __restrict__ probs,
                             const int* __restrict__ labels,
                             const int* __restrict__ groups,
                             const int* __restrict__ indices, int B) {
    int i = blockIdx.x * blockDim.x + threadIdx.x;
    if (i >= B) return;
    int idx = indices[i];
    if (g_winner[idx] != i + 1) return;
    unsigned oldside = g_side[idx];
    unsigned newside = enc(probs[i], labels[i], groups[i]);
    if (newside == oldside) return;
    int chunk = idx >> 9, seg = chunk >> 10;
    if (oldside & 0x80000000u) {
        unsigned b = (oldside >> 23) & 31u;
        unsigned long long d = C42 + (unsigned long long)(oldside & 0x7FFFFFu);
        atomicAdd(&g_p1[(size_t)b * NCHUNK + chunk], 0ull - d);
        atomicAdd(&g_segSum[b * NSEG + seg], 0ull - d);
    }
    if (newside & 0x80000000u) {
        unsigned b = (newside >> 23) & 31u;
        unsigned long long d = C42 + (unsigned long long)(newside & 0x7FFFFFu);
        atomicAdd(&g_p1[(size_t)b * NCHUNK + chunk], d);
        atomicAdd(&g_segSum[b * NSEG + seg], d);
    }
    g_side[idx] = newside;
}

// ---------------------------------------------------------------- planB
// stage byte: [1..62] clean stage; 0x80|ea = ea->ea+1 crossing candidate;
// 0xFF = full element walk.
__global__ void __launch_bounds__(256)
planB_kernel() {
    int seg = blockIdx.x, b = blockIdx.y, t = threadIdx.x;
    __shared__ unsigned long long ss[NSEG];
    __shared__ unsigned long long sc[256];
    __shared__ unsigned long long segpre_sh;
    if (t < NSEG) ss[t] = g_segSum[b * NSEG + t];
    __syncthreads();
    if (t == 0) {
        unsigned long long p = 0ull;
        for (int i = 0; i < seg; i++) p += ss[i];
        segpre_sh = p;
        if (seg == NSEG - 1) g_cntTot[b] = (p + ss[NSEG - 1]) >> 42;
    }
    __syncthreads();

    size_t base = (size_t)b * NCHUNK + seg * 1024 + t * 4;
    const ulonglong2* pp = reinterpret_cast<const ulonglong2*>(&g_p1[base]);
    ulonglong2 v01 = pp[0], v23 = pp[1];
    unsigned long long pv[4] = { v01.x, v01.y, v23.x, v23.y };
    sc[t] = pv[0] + pv[1] + pv[2] + pv[3];
    __syncthreads();
    for (int off = 1; off < 256; off <<= 1) {
        unsigned long long v = (t >= off) ? sc[t - off] : 0ull;
        __syncthreads();
        sc[t] += v;
        __syncthreads();
    }
    unsigned long long excl = (t > 0) ? sc[t - 1] : 0ull;
    unsigned long long P = (segpre_sh + excl) & M42;   // raw prefix (2^-23 units)

    unsigned char st4[4];
#pragma unroll
    for (int k = 0; k < 4; k++) {
        unsigned long long cs = pv[k] & M42;
        unsigned cnt = (unsigned)(pv[k] >> 42);
        unsigned char st;
        if (cnt == 0u) {
            st = 1;                               // empty chunk: clean, inc 0
        } else {
            unsigned long long hi = P + cs;
            int e2 = 63 - __clzll((long long)hi) - 23;
            if (e2 < 1) st = 0xFF;
            else {
                int sb = (3 * e2) / 2 + 2; if (sb > 40) sb = 40;
                unsigned long long sl = (1ull << sb) + (1ull << 22);
                if (P > sl) {
                    unsigned long long lo2 = P - sl, hi2 = hi + sl;
                    int ea = 63 - __clzll((long long)lo2) - 23;
                    int eb = 63 - __clzll((long long)hi2) - 23;
                    if (ea >= 1 && ea == eb)           st = (unsigned char)ea;
                    else if (ea >= 1 && eb == ea + 1)  st = (unsigned char)(0x80 | ea);
                    else                               st = 0xFF;
                } else st = 0xFF;
            }
        }
        st4[k] = st;
        P += cs;
    }
    *reinterpret_cast<uchar4*>(&g_stage[base]) =
        make_uchar4(st4[0], st4[1], st4[2], st4[3]);
}

// ---------------------------------------------------------------- pass2
__global__ void __launch_bounds__(256)
pass2_kernel() {
    __shared__ unsigned acc[8][NB * 32];
    __shared__ unsigned long long tr[NB][8];
    __shared__ unsigned char stg[8][NB];
    int t = threadIdx.x, w = t >> 5, lane = t & 31;
    int chunk0 = blockIdx.x * 8, chunk = chunk0 + w;
    int seg = chunk0 >> 10;
    stg[w][lane] = g_stage[(size_t)lane * NCHUNK + chunk];
    unsigned* A = acc[w];
#pragma unroll
    for (int b = 0; b < NB; b++) A[b * 32 + lane] = 0u;
    __syncwarp();
    int base4 = chunk * (CH / 4);
    const uint4* side4 = reinterpret_cast<const uint4*>(g_side);
    uint4 sdv[4];
#pragma unroll
    for (int k = 0; k < 4; k++) sdv[k] = side4[base4 + k * 32 + lane];
#pragma unroll
    for (int k = 0; k < 4; k++) {
        unsigned ds[4] = { sdv[k].x, sdv[k].y, sdv[k].z, sdv[k].w };
#pragma unroll
        for (int c = 0; c < 4; c++) {
            unsigned side = ds[c];
            if (side & 0x80000000u) {
                unsigned b = (side >> 23) & 31u;
                int e = stg[w][b];
                if (e < 0x80) {
                    unsigned j = side & 0x7FFFFFu;
                    A[b * 32 + lane] += rne_q(j, e) << e;
                }
            }
        }
    }
    __syncwarp();
    unsigned long long tot = 0ull;
#pragma unroll
    for (int k = 0; k < 32; k++)
        tot += (unsigned long long)A[lane * 32 + ((lane + k) & 31)];
    tr[lane][w] = tot;
    __syncthreads();
    int b = t >> 3, cw = t & 7;
    unsigned long long pv = tr[b][cw];            // boundary chunks: pv==0
    g_inc[(size_t)b * NCHUNK + chunk0 + cw] = pv;
    int bd = (stg[cw][b] & 0x80) ? 1 : 0;
    unsigned long long sv = pv;
    sv += __shfl_down_sync(0xFFFFFFFFu, sv, 4, 8);
    sv += __shfl_down_sync(0xFFFFFFFFu, sv, 2, 8);
    sv += __shfl_down_sync(0xFFFFFFFFu, sv, 1, 8);
    bd += __shfl_down_sync(0xFFFFFFFFu, bd, 4, 8);
    bd += __shfl_down_sync(0xFFFFFFFFu, bd, 2, 8);
    bd += __shfl_down_sync(0xFFFFFFFFu, bd, 1, 8);
    if (cw == 0) {
        atomicAdd(&g_osegC[b * NSEG + seg], sv);
        if (bd) atomicAdd(&g_osegB[b * NSEG + seg], bd);
    }
}

// ---------------------------------------------------------------- orchB
__global__ void __launch_bounds__(256)
orchB_kernel() {
    int seg = blockIdx.x, b = blockIdx.y, t = threadIdx.x;
    __shared__ unsigned long long ssC[NSEG];
    __shared__ int ssB[NSEG];
    __shared__ unsigned long long scC[256];
    __shared__ int scB[256];
    __shared__ unsigned long long segC_sh;
    __shared__ int segB_sh;
    __shared__ int locCh[LCAP];
    __shared__ int locKp[LCAP];
    __shared__ int locN;
    __shared__ unsigned jb[JCAP];
    __shared__ int wcnt[8];
    __shared__ int phN;
    int w = t >> 5, lane = t & 31;
    if (t == 0) locN = 0;
    if (t < NSEG) { ssC[t] = g_osegC[b * NSEG + t]; ssB[t] = g_osegB[b * NSEG + t]; }
    __syncthreads();
    if (t == 0) {
        unsigned long long pc = 0ull; int pb = 0;
        for (int i = 0; i < seg; i++) { pc += ssC[i]; pb += ssB[i]; }
        segC_sh = pc; segB_sh = pb;
        if (seg == NSEG - 1) {
            g_cleanTot[b] = pc + ssC[NSEG - 1];
            g_nBnd[b]     = pb + ssB[NSEG - 1];
        }
    }
    __syncthreads();

    size_t base = (size_t)b * NCHUNK + seg * 1024 + t * 4;
    uchar4 st4 = *reinterpret_cast<const uchar4*>(&g_stage[base]);
    const ulonglong2* ip = reinterpret_cast<const ulonglong2*>(&g_inc[base]);
    ulonglong2 i01 = ip[0], i23 = ip[1];
    unsigned long long inc[4] = { i01.x, i01.y, i23.x, i23.y };
    unsigned char sts[4] = { st4.x, st4.y, st4.z, st4.w };

    unsigned long long pc = 0ull; int pb = 0;
#pragma unroll
    for (int k = 0; k < 4; k++) {
        if (sts[k] & 0x80) pb++;
        else pc += inc[k];
    }
    scC[t] = pc; scB[t] = pb;
    __syncthreads();
    for (int off = 1; off < 256; off <<= 1) {
        unsigned long long vC = (t >= off) ? scC[t - off] : 0ull;
        int vB = (t >= off) ? scB[t - off] : 0;
        __syncthreads();
        scC[t] += vC; scB[t] += vB;
        __syncthreads();
    }
    unsigned long long run = segC_sh + ((t > 0) ? scC[t - 1] : 0ull);
    int kpos = segB_sh + ((t > 0) ? scB[t - 1] : 0);
#pragma unroll
    for (int k = 0; k < 4; k++) {
        if (sts[k] & 0x80) {
            if (kpos < BCAP) {
                g_bndPre[b * BCAP + kpos] = run;
                int sl = atomicAdd(&locN, 1);
                if (sl < LCAP) {
                    locCh[sl] = seg * 1024 + t * 4 + k;
                    locKp[sl] = kpos;
                }
            }
            kpos++;
        } else run += inc[k];
    }
    __syncthreads();

    // inline gather per local boundary chunk (order-preserving compaction)
    int nloc = locN; if (nloc > LCAP) nloc = LCAP;
    for (int e = 0; e < nloc; e++) {
        int ch = locCh[e];
        unsigned* rec = &g_bndJ[(size_t)(b * BCAP + locKp[e]) * RECW];
        int cnt = 0;
        for (int ph = 0; ph < 2; ph++) {
            unsigned side = g_side[ch * CH + ph * 256 + t];
            bool valid = (side & 0x80000000u) &&
                         (((side >> 23) & 31u) == (unsigned)b);
            unsigned m = __ballot_sync(0xFFFFFFFFu, valid);
            if (lane == 0) wcnt[w] = __popc(m);
            __syncthreads();
            if (t == 0) {
                int s = 0;
                for (int q = 0; q < 8; q++) { int c = wcnt[q]; wcnt[q] = s; s += c; }
                phN = s;
            }
            __syncthreads();
            if (valid) {
                int pos = cnt + wcnt[w] + __popc(m & ((1u << lane) - 1u));
                if (pos < JCAP) jb[pos] = side & 0x7FFFFFu;
            }
            cnt += phN;
            __syncthreads();
        }
        if (t == 0) {
            if (cnt > JCAP) cnt = JCAP;
            unsigned st = g_stage[(size_t)b * NCHUNK + ch];
            rec[0] = (unsigned)cnt | (st << 16);
            for (int c = 0; c < cnt; c++) rec[1 + c] = jb[c];
            if ((st & 0x80) && st != 0xFFu) {
                int ea = (int)(st & 0x7Fu);
                unsigned iA = 0u, iB = 0u;
                for (int c = 0; c < cnt; c++) {
                    unsigned j = jb[c];
                    iA += rne_q(j, ea) << ea;
                    iB += rne_q(j, ea + 1) << (ea + 1);
                }
                rec[RECW - 2] = iA;
                rec[RECW - 1] = iB;
            }
        }
        __syncthreads();
    }
}

// Bit-exact IEEE f32 RNE add; v = accumulator*2^23 (<=24 sig bits), j<2^23.
__device__ __forceinline__ unsigned long long emul_add(unsigned long long v,
                                                       unsigned long long j) {
    unsigned long long tt = v + j;
    if (tt == 0ull) return 0ull;
    int nb = 64 - __clzll((long long)tt);
    if (nb <= 24) return tt;
    int sh = nb - 24;
    unsigned long long half = 1ull << (sh - 1);
    unsigned long long r = tt & ((1ull << sh) - 1ull);
    unsigned long long q = tt >> sh;
    q += (unsigned long long)((r > half) || (r == half && (q & 1ull)));
    return q << sh;
}

// ---------------------------------------------------------------- finalize
__device__ void finalize_body(float* out) {
    float var2[2], nn2[2];
    for (int lab = 0; lab < 2; lab++) {
        float avg[16], incl[16];
        for (int g = 0; g < 16; g++) {
            int b = lab + 2 * g;
            float sum = g_S[b];
            float cnt = (float)(long long)g_cntTot[b];
            avg[g]  = __fdiv_rn(sum, fmaxf(cnt, 1.0f));
            incl[g] = (cnt >= 10.0f) ? 1.0f : 0.0f;
        }
        float n = 0.0f, msum = 0.0f;
        for (int g = 0; g < 16; g++) {
            n    = __fadd_rn(n, incl[g]);
            msum = __fadd_rn(msum, __fmul_rn(avg[g], incl[g]));
        }
        float mean = __fdiv_rn(msum, fmaxf(n, 1.0f));
        float vsum = 0.0f;
        for (int g = 0; g < 16; g++) {
            float d  = __fadd_rn(avg[g], -mean);
            float d2 = __fmul_rn(d, d);
            vsum = __fadd_rn(vsum, __fmul_rn(incl[g], d2));
        }
        float var = __fdiv_rn(vsum, fmaxf(__fadd_rn(n, -1.0f), 1.0f));
        var2[lab] = var; nn2[lab] = n;
    }
    bool pos_ok = nn2[1] >= 2.0f, neg_ok = nn2[0] >= 2.0f;
    float loss;
    if (pos_ok && neg_ok) loss = __fmul_rn(0.5f, __fadd_rn(var2[1], var2[0]));
    else if (pos_ok)      loss = var2[1];
    else if (neg_ok)      loss = var2[0];
    else                  loss = 0.0f;
    out[0] = loss;
}

// ---------------------------------------------------------------- orchF
__global__ void __launch_bounds__(512)
orchF_kernel(float* __restrict__ out) {
    int b = blockIdx.x, t = threadIdx.x;
    __shared__ unsigned jrec[SMAX * RECW];
    __shared__ unsigned long long pre[SMAX];
    int nBnd = g_nBnd[b];
    if (nBnd > BCAP) nBnd = BCAP;

    unsigned long long v = 0ull, consumed = 0ull;
    for (int base = 0; base < nBnd; base += SMAX) {
        int nb2 = nBnd - base; if (nb2 > SMAX) nb2 = SMAX;
        const unsigned* src = &g_bndJ[(size_t)(b * BCAP + base) * RECW];
        for (int i = t; i < nb2 * RECW; i += 512) jrec[i] = src[i];
        for (int i = t; i < nb2; i += 512) pre[i] = g_bndPre[b * BCAP + base + i];
        __syncthreads();
        if (t == 0) {
            for (int kk = 0; kk < nb2; kk++) {
                v += pre[kk] - consumed;   // exact integer clean incs between
                consumed = pre[kk];
                const unsigned* r = &jrec[kk * RECW];
                unsigned hdr = r[0];
                int cnt = (int)(hdr & 0xFFFFu);
                unsigned st = hdr >> 16;
                bool done = false;
                if ((st & 0x80u) && st != 0xFFu && v >= (1ull << 23)) {
                    int ea = (int)(st & 0x7Fu);
                    int ev = 63 - __clzll((long long)v) - 23;
                    if (ev == ea) {
                        unsigned long long nv = v + (unsigned long long)r[RECW - 2];
                        if (63 - __clzll((long long)nv) - 23 == ea) { v = nv; done = true; }
                    } else if (ev == ea + 1) {
                        unsigned long long nv = v + (unsigned long long)r[RECW - 1];
                        if (63 - __clzll((long long)nv) - 23 == ea + 1) { v = nv; done = true; }
                    }
                }
                if (!done) {
                    for (int c = 1; c <= cnt; c++)
                        v = emul_add(v, (unsigned long long)r[c]);
                }
            }
        }
        __syncthreads();
    }
    if (t == 0) {
        v += g_cleanTot[b] - consumed;
        g_S[b] = (float)((double)v * (1.0 / 8388608.0));   // <=24 sig bits: exact
        __threadfence();
        unsigned prev = atomicAdd(&g_done, 1u);
        if (prev == NB - 1u) {
            g_done = 0u;               // self-reset for graph replay
            __threadfence();
            finalize_body(out);
        }
    }
}

// ---------------------------------------------------------------- launch
extern "C" void kernel_launch(void* const* d_in, const int* in_sizes, int n_in,
                              void* d_out, int out_size) {
    const float* probs   = (const float*)d_in[0];
    const int*   labels  = (const int*)d_in[1];
    const int*   groups  = (const int*)d_in[2];
    const int*   indices = (const int*)d_in[3];
    const float* sbuf    = (const float*)d_in[4];
    const int*   lbuf    = (const int*)d_in[5];
    const int*   gbuf    = (const int*)d_in[6];
    int B = in_sizes[0];

    zeromark_kernel<<<(B + 255) / 256, 256>>>(indices, B);
    pass1_kernel<<<NCHUNK / 8, 256>>>((const float4*)sbuf, (const int4*)lbuf,
                                      (const int4*)gbuf);
    patch_kernel<<<(B + 127) / 128, 128>>>(probs, labels, groups, indices, B);
    planB_kernel<<<dim3(NSEG, NB), 256>>>();
    pass2_kernel<<<NCHUNK / 8, 256>>>();
    orchB_kernel<<<dim3(NSEG, NB), 256>>>();
    orchF_kernel<<<NB, 512>>>((float*)d_out);
}